// round 3
// baseline (speedup 1.0000x reference)
#include <cuda_runtime.h>

#define BB 8
#define NN 2048
#define HID 768
#define NH 4
#define VOC 15
#define ROWS (BB*NN)       // 16384
#define K2DIM (NH*HID)     // 3072

// ---------------- scratch (static device globals; no allocation) -------------
__device__ float    g_xcat[ROWS*K2DIM];     // layer-1 concat output (B,N,3072)
__device__ float    g_Wh  [ROWS*HID];       // layer-2 Wh
__device__ unsigned g_adjbits[ROWS*64];     // adjacency bitmask, 64 words/row
__device__ int      g_C   [ROWS*16];        // neighbor vocab counts (pad 16)
__device__ int      g_H   [BB*16];          // per-batch vocab histogram (fallback)
__device__ float    g_T   [NH*VOC*HID];     // embed@W per head
__device__ float    g_E   [NH*VOC*16];      // exp(leaky(t1+t2)) table (pad 16)
__device__ float    g_s1  [ROWS];
__device__ float    g_s2  [ROWS];

__device__ __forceinline__ float leakyf(float x){ return x > 0.f ? x : 0.2f*x; }
__device__ __forceinline__ float eluf(float x){ return x > 0.f ? x : (__expf(x)-1.f); }

// ---------------- K0: zero output accumulator --------------------------------
__global__ void k_zero(float* __restrict__ out){
    int t = blockIdx.x*256 + threadIdx.x;
    if (t < BB*HID) out[t] = 0.f;
}

// ---------------- K1: T_h = embed @ W_h  (15x768 per head) -------------------
__global__ void k_T(const float* __restrict__ embed, const float* __restrict__ Wheads){
    __shared__ float emb[VOC*HID];
    int h = blockIdx.y;
    int c = blockIdx.x*128 + threadIdx.x;
    for (int i = threadIdx.x; i < VOC*HID; i += 128) emb[i] = embed[i];
    __syncthreads();
    float acc[VOC];
    #pragma unroll
    for (int v = 0; v < VOC; v++) acc[v] = 0.f;
    const float* Wp = Wheads + (size_t)h*HID*HID + c;
    for (int k = 0; k < HID; k++){
        float w = Wp[(size_t)k*HID];
        #pragma unroll
        for (int v = 0; v < VOC; v++) acc[v] += emb[v*HID + k] * w;
    }
    #pragma unroll
    for (int v = 0; v < VOC; v++) g_T[(h*VOC + v)*HID + c] = acc[v];
}

// ---------------- K2: t1/t2 and E table --------------------------------------
__global__ void k_pre2(const float* __restrict__ aheads){
    __shared__ float t1s[NH*VOC], t2s[NH*VOC];
    int t = threadIdx.x;
    if (t < NH*VOC){
        int h = t / VOC, v = t % VOC;
        const float* Tp = g_T + (h*VOC + v)*HID;
        const float* a  = aheads + h*2*HID;
        float s1 = 0.f, s2 = 0.f;
        for (int c = 0; c < HID; c++){ s1 += Tp[c]*a[c]; s2 += Tp[c]*a[HID + c]; }
        t1s[t] = s1; t2s[t] = s2;
    }
    __syncthreads();
    for (int i = t; i < NH*VOC*VOC; i += blockDim.x){
        int h = i/(VOC*VOC); int u = (i/VOC)%VOC; int v = i%VOC;
        g_E[(h*VOC + u)*16 + v] = expf(leakyf(t1s[h*VOC + u] + t2s[h*VOC + v]));
    }
}

// ---------------- K3: adjacency bitmask + neighbor vocab counts --------------
__global__ void k_adj(const int* __restrict__ nf, const int* __restrict__ adj){
    __shared__ int fs[NN];
    __shared__ unsigned vmask[VOC][64];
    int b  = blockIdx.x >> 8;          // 256 blocks per batch, 8 rows per block
    int r0 = (blockIdx.x & 255) * 8;
    int tid = threadIdx.x, lane = tid & 31, wi = tid >> 5;
    for (int i = tid; i < NN; i += 256) fs[i] = nf[b*NN + i];
    __syncthreads();
    // vocab bitmasks
    for (int w = wi*8; w < wi*8 + 8; w++){
        int fj = fs[w*32 + lane];
        #pragma unroll
        for (int v = 0; v < VOC; v++){
            unsigned m = __ballot_sync(0xffffffffu, fj == v);
            if (lane == 0) vmask[v][w] = m;
        }
    }
    __syncthreads();
    // per-batch histogram (for the all-masked fallback), written once per batch
    if ((blockIdx.x & 255) == 0 && wi == 0){
        #pragma unroll
        for (int v = 0; v < VOC; v++){
            unsigned hv = __popc(vmask[v][lane]) + __popc(vmask[v][lane + 32]);
            hv = __reduce_add_sync(0xffffffffu, hv);
            if (lane == 0) g_H[b*16 + v] = (int)hv;
        }
    }
    // one warp per row: adjacency bits + counts
    int r = r0 + wi;
    const int* arow = adj + (size_t)(b*NN + r) * NN;
    unsigned am0 = 0, am1 = 0;
    for (int ch = 0; ch < 64; ch++){
        int a = arow[ch*32 + lane];
        unsigned m = __ballot_sync(0xffffffffu, a > 0);
        if (ch == lane)      am0 = m;
        if (ch == lane + 32) am1 = m;
    }
    unsigned* abp = g_adjbits + (size_t)(b*NN + r)*64;
    abp[lane] = am0; abp[32 + lane] = am1;
    #pragma unroll
    for (int v = 0; v < VOC; v++){
        unsigned c = __popc(am0 & vmask[v][lane]) + __popc(am1 & vmask[v][lane + 32]);
        c = __reduce_add_sync(0xffffffffu, c);
        if (lane == 0) g_C[(b*NN + r)*16 + v] = (int)c;
    }
}

// ---------------- K4: layer-1 output -> xcat (K=15 GEMM + elu) ---------------
__global__ void __launch_bounds__(256) k_l1(const int* __restrict__ nf){
    __shared__ float ws[128][16];
    __shared__ float Tt[VOC][128];
    int h = blockIdx.y / 6, ct = blockIdx.y % 6;
    int grow0 = blockIdx.x * 128;
    int b = grow0 / NN;
    int tid = threadIdx.x;
    if (tid < 128){
        int grow = grow0 + tid;
        int fi = nf[grow];
        const float* Ep = g_E + (h*VOC + fi)*16;
        const int*   Cp = g_C + (size_t)grow*16;
        float cv[VOC]; float den = 0.f;
        #pragma unroll
        for (int v = 0; v < VOC; v++){ cv[v] = (float)Cp[v]; den += cv[v]*Ep[v]; }
        if (den > 0.f){
            float inv = 1.f/den;
            #pragma unroll
            for (int v = 0; v < VOC; v++) ws[tid][v] = cv[v]*Ep[v]*inv;
        } else {
            const int* Hp = g_H + b*16;
            #pragma unroll
            for (int v = 0; v < VOC; v++) ws[tid][v] = (float)Hp[v] * (1.f/(float)NN);
        }
    }
    for (int i = tid; i < VOC*128; i += 256){
        int v = i >> 7, c = i & 127;
        Tt[v][c] = g_T[(h*VOC + v)*HID + ct*128 + c];
    }
    __syncthreads();
    int tr = tid >> 4, tc = tid & 15;
    float acc[8][8];
    #pragma unroll
    for (int i = 0; i < 8; i++)
        #pragma unroll
        for (int j = 0; j < 8; j++) acc[i][j] = 0.f;
    #pragma unroll
    for (int v = 0; v < VOC; v++){
        float bb[8];
        #pragma unroll
        for (int j = 0; j < 8; j++) bb[j] = Tt[v][tc*8 + j];
        #pragma unroll
        for (int i = 0; i < 8; i++){
            float a = ws[tr*8 + i][v];
            #pragma unroll
            for (int j = 0; j < 8; j++) acc[i][j] += a*bb[j];
        }
    }
    #pragma unroll
    for (int i = 0; i < 8; i++){
        float* op = g_xcat + (size_t)(grow0 + tr*8 + i)*K2DIM + h*HID + ct*128 + tc*8;
        float4 v0 = make_float4(eluf(acc[i][0]), eluf(acc[i][1]), eluf(acc[i][2]), eluf(acc[i][3]));
        float4 v1 = make_float4(eluf(acc[i][4]), eluf(acc[i][5]), eluf(acc[i][6]), eluf(acc[i][7]));
        *(float4*)op = v0; *(float4*)(op + 4) = v1;
    }
}

// ---------------- K5: big GEMM  Wh = xcat @ W_out  (16384x768x3072) ----------
__global__ void __launch_bounds__(256,2) k_gemm(const float* __restrict__ Wout){
    __shared__ float As[2][16][128];
    __shared__ float Bs[2][16][128];
    int n0 = blockIdx.x * 128;
    int m0 = blockIdx.y * 128;
    int tid = threadIdx.x;
    int tr = tid >> 4, tc = tid & 15;
    int am = tid >> 1;                    // A: row within tile
    int ak = (tid & 1) * 8;               // A: k offset (8 floats)
    int bk = tid >> 4;                    // B: k row
    int bc = (tid & 15) * 8;              // B: col offset
    const float* Ap = g_xcat + (size_t)(m0 + am)*K2DIM + ak;
    const float* Bp = Wout + (size_t)bk*HID + n0 + bc;
    float4 ra0 = *(const float4*)(Ap);
    float4 ra1 = *(const float4*)(Ap + 4);
    float4 rb0 = *(const float4*)(Bp);
    float4 rb1 = *(const float4*)(Bp + 4);
    As[0][ak+0][am]=ra0.x; As[0][ak+1][am]=ra0.y; As[0][ak+2][am]=ra0.z; As[0][ak+3][am]=ra0.w;
    As[0][ak+4][am]=ra1.x; As[0][ak+5][am]=ra1.y; As[0][ak+6][am]=ra1.z; As[0][ak+7][am]=ra1.w;
    *(float4*)&Bs[0][bk][bc] = rb0; *(float4*)&Bs[0][bk][bc+4] = rb1;
    __syncthreads();
    float acc[8][8];
    #pragma unroll
    for (int i = 0; i < 8; i++)
        #pragma unroll
        for (int j = 0; j < 8; j++) acc[i][j] = 0.f;
    const int NK = K2DIM/16;  // 192
    for (int kt = 0; kt < NK; kt++){
        int cur = kt & 1, nxt = cur ^ 1;
        if (kt + 1 < NK){
            const float* Ap2 = Ap + (kt+1)*16;
            const float* Bp2 = Bp + (size_t)(kt+1)*16*HID;
            ra0 = *(const float4*)Ap2; ra1 = *(const float4*)(Ap2 + 4);
            rb0 = *(const float4*)Bp2; rb1 = *(const float4*)(Bp2 + 4);
        }
        #pragma unroll
        for (int kk = 0; kk < 16; kk++){
            float av[8], bv[8];
            *(float4*)av     = *(float4*)&As[cur][kk][tr*8];
            *(float4*)(av+4) = *(float4*)&As[cur][kk][tr*8+4];
            *(float4*)bv     = *(float4*)&Bs[cur][kk][tc*8];
            *(float4*)(bv+4) = *(float4*)&Bs[cur][kk][tc*8+4];
            #pragma unroll
            for (int i = 0; i < 8; i++)
                #pragma unroll
                for (int j = 0; j < 8; j++) acc[i][j] += av[i]*bv[j];
        }
        if (kt + 1 < NK){
            As[nxt][ak+0][am]=ra0.x; As[nxt][ak+1][am]=ra0.y; As[nxt][ak+2][am]=ra0.z; As[nxt][ak+3][am]=ra0.w;
            As[nxt][ak+4][am]=ra1.x; As[nxt][ak+5][am]=ra1.y; As[nxt][ak+6][am]=ra1.z; As[nxt][ak+7][am]=ra1.w;
            *(float4*)&Bs[nxt][bk][bc] = rb0; *(float4*)&Bs[nxt][bk][bc+4] = rb1;
        }
        __syncthreads();
    }
    float* Op = g_Wh + (size_t)(m0 + tr*8)*HID + n0 + tc*8;
    #pragma unroll
    for (int i = 0; i < 8; i++){
        *(float4*)(Op + (size_t)i*HID)     = make_float4(acc[i][0], acc[i][1], acc[i][2], acc[i][3]);
        *(float4*)(Op + (size_t)i*HID + 4) = make_float4(acc[i][4], acc[i][5], acc[i][6], acc[i][7]);
    }
}

// ---------------- K6: s1 = Wh . a_out[:768], s2 = Wh . a_out[768:] -----------
__global__ void k_s12(const float* __restrict__ aout){
    int tid = threadIdx.x, lane = tid & 31, wi = tid >> 5;
    int row = blockIdx.x*8 + wi;
    const float* Whp = g_Wh + (size_t)row*HID;
    float s1 = 0.f, s2 = 0.f;
    for (int c = lane; c < HID; c += 32){
        float w = Whp[c];
        s1 += w * aout[c];
        s2 += w * aout[HID + c];
    }
    #pragma unroll
    for (int o = 16; o; o >>= 1){
        s1 += __shfl_xor_sync(0xffffffffu, s1, o);
        s2 += __shfl_xor_sync(0xffffffffu, s2, o);
    }
    if (lane == 0){ g_s1[row] = s1; g_s2[row] = s2; }
}

// ---------------- K7: fused masked-softmax attention GEMM + elu + mean pool --
__global__ void __launch_bounds__(256,2) k_attn(float* __restrict__ out){
    __shared__ float Whs[32][128];
    __shared__ float Aw [32][128];
    __shared__ float denS[256];
    __shared__ float colsum[128];
    int it = blockIdx.x, ct = blockIdx.y, b = blockIdx.z;
    int tid = threadIdx.x;
    int r = tid & 127, half = tid >> 7;
    int rowbase = b*NN + it*128;
    float s1r = g_s1[rowbase + r];
    const unsigned* abp = g_adjbits + (size_t)(rowbase + r)*64;
    const float* s2p = g_s2 + b*NN;
    int lkk = tid >> 3;              // 0..31 (Wh load row)
    int lc  = (tid & 7) * 16;        // Wh load col group
    const float* WhB = g_Wh + (size_t)b*NN*HID + ct*128;
    int tr = tid >> 4, tc = tid & 15;
    if (tid < 128) colsum[tid] = 0.f;
    float acc[8][8];
    #pragma unroll
    for (int i = 0; i < 8; i++)
        #pragma unroll
        for (int j = 0; j < 8; j++) acc[i][j] = 0.f;
    float dpart = 0.f;
    for (int kt = 0; kt < 64; kt++){
        const float* wp = WhB + (size_t)(kt*32 + lkk)*HID + lc;
        float4 w0 = *(const float4*)wp;
        float4 w1 = *(const float4*)(wp + 4);
        float4 w2 = *(const float4*)(wp + 8);
        float4 w3 = *(const float4*)(wp + 12);
        // generate attention weights while loads are in flight
        unsigned word = abp[kt];
        #pragma unroll
        for (int q = 0; q < 16; q++){
            int kk = half*16 + q;
            float w = 0.f;
            if ((word >> kk) & 1u){
                w = __expf(leakyf(s1r + s2p[kt*32 + kk]));
                dpart += w;
            }
            Aw[kk][r] = w;
        }
        *(float4*)&Whs[lkk][lc]      = w0;
        *(float4*)&Whs[lkk][lc + 4]  = w1;
        *(float4*)&Whs[lkk][lc + 8]  = w2;
        *(float4*)&Whs[lkk][lc + 12] = w3;
        __syncthreads();
        #pragma unroll
        for (int kk = 0; kk < 32; kk++){
            float av[8], bv[8];
            *(float4*)av     = *(float4*)&Aw[kk][tr*8];
            *(float4*)(av+4) = *(float4*)&Aw[kk][tr*8+4];
            *(float4*)bv     = *(float4*)&Whs[kk][tc*8];
            *(float4*)(bv+4) = *(float4*)&Whs[kk][tc*8+4];
            #pragma unroll
            for (int i = 0; i < 8; i++)
                #pragma unroll
                for (int j = 0; j < 8; j++) acc[i][j] += av[i]*bv[j];
        }
        __syncthreads();
    }
    denS[tid] = dpart;
    __syncthreads();
    float csum[8];
    #pragma unroll
    for (int j = 0; j < 8; j++) csum[j] = 0.f;
    #pragma unroll
    for (int i = 0; i < 8; i++){
        int lr = tr*8 + i;
        float den = denS[lr] + denS[128 + lr];
        float inv = (den > 0.f) ? 1.f/den : 0.f;
        #pragma unroll
        for (int j = 0; j < 8; j++){
            float h = eluf(acc[i][j] * inv);
            csum[j] += h;
        }
    }
    #pragma unroll
    for (int j = 0; j < 8; j++) atomicAdd(&colsum[tc*8 + j], csum[j]);
    __syncthreads();
    if (tid < 128)
        atomicAdd(&out[b*HID + ct*128 + tid], colsum[tid] * (1.f/(float)NN));
}

// ---------------- launch ------------------------------------------------------
extern "C" void kernel_launch(void* const* d_in, const int* in_sizes, int n_in,
                              void* d_out, int out_size){
    const int*   nf     = (const int*)d_in[0];
    const int*   adj    = (const int*)d_in[1];
    const float* embed  = (const float*)d_in[2];
    const float* Wheads = (const float*)d_in[3];
    const float* aheads = (const float*)d_in[4];
    const float* Wout   = (const float*)d_in[5];
    const float* aout   = (const float*)d_in[6];
    float* out = (float*)d_out;

    k_zero<<<24, 256>>>(out);
    k_T  <<<dim3(6, 4), 128>>>(embed, Wheads);
    k_pre2<<<1, 64>>>(aheads);
    k_adj<<<2048, 256>>>(nf, adj);
    k_l1 <<<dim3(128, 24), 256>>>(nf);
    k_gemm<<<dim3(6, 128), 256>>>(Wout);
    k_s12<<<2048, 256>>>(aout);
    k_attn<<<dim3(16, 6, 8), 256>>>(out);
}

// round 5
// speedup vs baseline: 1.0042x; 1.0042x over previous
#include <cuda_runtime.h>

#define BB 8
#define NN 2048
#define HID 768
#define NH 4
#define VOC 15
#define ROWS (BB*NN)       // 16384
#define K2DIM (NH*HID)     // 3072

typedef unsigned long long u64;

// ---------------- packed f32x2 helpers (Blackwell FFMA2) ---------------------
__device__ __forceinline__ u64 pack2(float lo, float hi){
    u64 r; asm("mov.b64 %0, {%1, %2};" : "=l"(r) : "f"(lo), "f"(hi)); return r;
}
__device__ __forceinline__ void unpack2(u64 v, float &lo, float &hi){
    asm("mov.b64 {%0, %1}, %2;" : "=f"(lo), "=f"(hi) : "l"(v));
}
__device__ __forceinline__ void fma2(u64 &d, u64 a, u64 b){
    asm("fma.rn.f32x2 %0, %1, %2, %0;" : "+l"(d) : "l"(a), "l"(b));
}

__device__ __forceinline__ float leakyf(float x){ return x > 0.f ? x : 0.2f*x; }
__device__ __forceinline__ float eluf(float x){ return x > 0.f ? x : (__expf(x)-1.f); }

// ---------------- scratch (static device globals; no allocation) -------------
__device__ float    g_xcat[ROWS*K2DIM];     // layer-1 concat output (B,N,3072)
__device__ float    g_Wh  [ROWS*HID];       // layer-2 Wh
__device__ unsigned g_adjbits[ROWS*64];     // adjacency bitmask, 64 words/row
__device__ int      g_C   [ROWS*16];        // neighbor vocab counts (pad 16)
__device__ int      g_H   [BB*16];          // per-batch vocab histogram (fallback)
__device__ float    g_T   [NH*VOC*HID];     // embed@W per head
__device__ float    g_E   [NH*VOC*16];      // exp(leaky(t1+t2)) table (pad 16)
__device__ float    g_s1  [ROWS];
__device__ float    g_s2  [ROWS];

// ---------------- K0: zero output accumulator --------------------------------
__global__ void k_zero(float* __restrict__ out){
    int t = blockIdx.x*256 + threadIdx.x;
    if (t < BB*HID) out[t] = 0.f;
}

// ---------------- K1: T_h = embed @ W_h  (15x768 per head) -------------------
__global__ void k_T(const float* __restrict__ embed, const float* __restrict__ Wheads){
    __shared__ float emb[VOC*HID];
    int h = blockIdx.y;
    int c = blockIdx.x*128 + threadIdx.x;
    for (int i = threadIdx.x; i < VOC*HID; i += 128) emb[i] = embed[i];
    __syncthreads();
    float acc[VOC];
    #pragma unroll
    for (int v = 0; v < VOC; v++) acc[v] = 0.f;
    const float* Wp = Wheads + (size_t)h*HID*HID + c;
    for (int k = 0; k < HID; k++){
        float w = Wp[(size_t)k*HID];
        #pragma unroll
        for (int v = 0; v < VOC; v++) acc[v] += emb[v*HID + k] * w;
    }
    #pragma unroll
    for (int v = 0; v < VOC; v++) g_T[(h*VOC + v)*HID + c] = acc[v];
}

// ---------------- K2: t1/t2 and E table --------------------------------------
__global__ void k_pre2(const float* __restrict__ aheads){
    __shared__ float t1s[NH*VOC], t2s[NH*VOC];
    int t = threadIdx.x;
    if (t < NH*VOC){
        int h = t / VOC, v = t % VOC;
        const float* Tp = g_T + (h*VOC + v)*HID;
        const float* a  = aheads + h*2*HID;
        float s1 = 0.f, s2 = 0.f;
        for (int c = 0; c < HID; c++){ s1 += Tp[c]*a[c]; s2 += Tp[c]*a[HID + c]; }
        t1s[t] = s1; t2s[t] = s2;
    }
    __syncthreads();
    for (int i = t; i < NH*VOC*VOC; i += blockDim.x){
        int h = i/(VOC*VOC); int u = (i/VOC)%VOC; int v = i%VOC;
        g_E[(h*VOC + u)*16 + v] = expf(leakyf(t1s[h*VOC + u] + t2s[h*VOC + v]));
    }
}

// ---------------- K3: adjacency bitmask + neighbor vocab counts --------------
__global__ void k_adj(const int* __restrict__ nf, const int* __restrict__ adj){
    __shared__ int fs[NN];
    __shared__ unsigned vmask[VOC][64];
    int b  = blockIdx.x >> 8;          // 256 blocks per batch, 8 rows per block
    int r0 = (blockIdx.x & 255) * 8;
    int tid = threadIdx.x, lane = tid & 31, wi = tid >> 5;
    for (int i = tid; i < NN; i += 256) fs[i] = nf[b*NN + i];
    __syncthreads();
    // vocab bitmasks
    for (int w = wi*8; w < wi*8 + 8; w++){
        int fj = fs[w*32 + lane];
        #pragma unroll
        for (int v = 0; v < VOC; v++){
            unsigned m = __ballot_sync(0xffffffffu, fj == v);
            if (lane == 0) vmask[v][w] = m;
        }
    }
    __syncthreads();
    // per-batch histogram (for the all-masked fallback), written once per batch
    if ((blockIdx.x & 255) == 0 && wi == 0){
        #pragma unroll
        for (int v = 0; v < VOC; v++){
            unsigned hv = __popc(vmask[v][lane]) + __popc(vmask[v][lane + 32]);
            hv = __reduce_add_sync(0xffffffffu, hv);
            if (lane == 0) g_H[b*16 + v] = (int)hv;
        }
    }
    // one warp per row: adjacency bits + counts
    int r = r0 + wi;
    const int* arow = adj + (size_t)(b*NN + r) * NN;
    unsigned am0 = 0, am1 = 0;
    for (int ch = 0; ch < 64; ch++){
        int a = arow[ch*32 + lane];
        unsigned m = __ballot_sync(0xffffffffu, a > 0);
        if (ch == lane)      am0 = m;
        if (ch == lane + 32) am1 = m;
    }
    unsigned* abp = g_adjbits + (size_t)(b*NN + r)*64;
    abp[lane] = am0; abp[32 + lane] = am1;
    #pragma unroll
    for (int v = 0; v < VOC; v++){
        unsigned c = __popc(am0 & vmask[v][lane]) + __popc(am1 & vmask[v][lane + 32]);
        c = __reduce_add_sync(0xffffffffu, c);
        if (lane == 0) g_C[(b*NN + r)*16 + v] = (int)c;
    }
}

// ---------------- K4: layer-1 output -> xcat (K=15 GEMM + elu) ---------------
__global__ void __launch_bounds__(256) k_l1(const int* __restrict__ nf){
    __shared__ float ws[128][16];
    __shared__ float Tt[VOC][128];
    int h = blockIdx.y / 6, ct = blockIdx.y % 6;
    int grow0 = blockIdx.x * 128;
    int b = grow0 / NN;
    int tid = threadIdx.x;
    if (tid < 128){
        int grow = grow0 + tid;
        int fi = nf[grow];
        const float* Ep = g_E + (h*VOC + fi)*16;
        const int*   Cp = g_C + (size_t)grow*16;
        float cv[VOC]; float den = 0.f;
        #pragma unroll
        for (int v = 0; v < VOC; v++){ cv[v] = (float)Cp[v]; den += cv[v]*Ep[v]; }
        if (den > 0.f){
            float inv = 1.f/den;
            #pragma unroll
            for (int v = 0; v < VOC; v++) ws[tid][v] = cv[v]*Ep[v]*inv;
        } else {
            const int* Hp = g_H + b*16;
            #pragma unroll
            for (int v = 0; v < VOC; v++) ws[tid][v] = (float)Hp[v] * (1.f/(float)NN);
        }
    }
    for (int i = tid; i < VOC*128; i += 256){
        int v = i >> 7, c = i & 127;
        Tt[v][c] = g_T[(h*VOC + v)*HID + ct*128 + c];
    }
    __syncthreads();
    int tr = tid >> 4, tc = tid & 15;
    float acc[8][8];
    #pragma unroll
    for (int i = 0; i < 8; i++)
        #pragma unroll
        for (int j = 0; j < 8; j++) acc[i][j] = 0.f;
    #pragma unroll
    for (int v = 0; v < VOC; v++){
        float bb[8];
        #pragma unroll
        for (int j = 0; j < 8; j++) bb[j] = Tt[v][tc*8 + j];
        #pragma unroll
        for (int i = 0; i < 8; i++){
            float a = ws[tr*8 + i][v];
            #pragma unroll
            for (int j = 0; j < 8; j++) acc[i][j] += a*bb[j];
        }
    }
    #pragma unroll
    for (int i = 0; i < 8; i++){
        float* op = g_xcat + (size_t)(grow0 + tr*8 + i)*K2DIM + h*HID + ct*128 + tc*8;
        float4 v0 = make_float4(eluf(acc[i][0]), eluf(acc[i][1]), eluf(acc[i][2]), eluf(acc[i][3]));
        float4 v1 = make_float4(eluf(acc[i][4]), eluf(acc[i][5]), eluf(acc[i][6]), eluf(acc[i][7]));
        *(float4*)op = v0; *(float4*)(op + 4) = v1;
    }
}

// ---------------- K5: big GEMM  Wh = xcat @ W_out  (16384x768x3072) ----------
// packed-f32x2 microkernel: 8x8 outer product as 8x4 FFMA2
__global__ void __launch_bounds__(256,2) k_gemm(const float* __restrict__ Wout){
    __shared__ float As[2][16][128];
    __shared__ float Bs[2][16][128];
    int n0 = blockIdx.x * 128;
    int m0 = blockIdx.y * 128;
    int tid = threadIdx.x;
    int tr = tid >> 4, tc = tid & 15;
    int am = tid >> 1;                    // A: row within tile
    int ak = (tid & 1) * 8;               // A: k offset (8 floats)
    int bk = tid >> 4;                    // B: k row
    int bc = (tid & 15) * 8;              // B: col offset
    const float* Ap = g_xcat + (size_t)(m0 + am)*K2DIM + ak;
    const float* Bp = Wout + (size_t)bk*HID + n0 + bc;
    float4 ra0 = *(const float4*)(Ap);
    float4 ra1 = *(const float4*)(Ap + 4);
    float4 rb0 = *(const float4*)(Bp);
    float4 rb1 = *(const float4*)(Bp + 4);
    As[0][ak+0][am]=ra0.x; As[0][ak+1][am]=ra0.y; As[0][ak+2][am]=ra0.z; As[0][ak+3][am]=ra0.w;
    As[0][ak+4][am]=ra1.x; As[0][ak+5][am]=ra1.y; As[0][ak+6][am]=ra1.z; As[0][ak+7][am]=ra1.w;
    *(float4*)&Bs[0][bk][bc] = rb0; *(float4*)&Bs[0][bk][bc+4] = rb1;
    __syncthreads();
    u64 acc2[8][4];
    #pragma unroll
    for (int i = 0; i < 8; i++)
        #pragma unroll
        for (int j = 0; j < 4; j++) acc2[i][j] = 0ull;
    const int NK = K2DIM/16;  // 192
    for (int kt = 0; kt < NK; kt++){
        int cur = kt & 1, nxt = cur ^ 1;
        if (kt + 1 < NK){
            const float* Ap2 = Ap + (kt+1)*16;
            const float* Bp2 = Bp + (size_t)(kt+1)*16*HID;
            ra0 = *(const float4*)Ap2; ra1 = *(const float4*)(Ap2 + 4);
            rb0 = *(const float4*)Bp2; rb1 = *(const float4*)(Bp2 + 4);
        }
        #pragma unroll
        for (int kk = 0; kk < 16; kk++){
            float av[8];
            *(float4*)av     = *(float4*)&As[cur][kk][tr*8];
            *(float4*)(av+4) = *(float4*)&As[cur][kk][tr*8+4];
            u64 b2[4];
            ulonglong2 t0 = *(const ulonglong2*)&Bs[cur][kk][tc*8];
            ulonglong2 t1 = *(const ulonglong2*)&Bs[cur][kk][tc*8+4];
            b2[0]=t0.x; b2[1]=t0.y; b2[2]=t1.x; b2[3]=t1.y;
            #pragma unroll
            for (int i = 0; i < 8; i++){
                u64 a2 = pack2(av[i], av[i]);
                #pragma unroll
                for (int j = 0; j < 4; j++) fma2(acc2[i][j], a2, b2[j]);
            }
        }
        if (kt + 1 < NK){
            As[nxt][ak+0][am]=ra0.x; As[nxt][ak+1][am]=ra0.y; As[nxt][ak+2][am]=ra0.z; As[nxt][ak+3][am]=ra0.w;
            As[nxt][ak+4][am]=ra1.x; As[nxt][ak+5][am]=ra1.y; As[nxt][ak+6][am]=ra1.z; As[nxt][ak+7][am]=ra1.w;
            *(float4*)&Bs[nxt][bk][bc] = rb0; *(float4*)&Bs[nxt][bk][bc+4] = rb1;
        }
        __syncthreads();
    }
    float* Op = g_Wh + (size_t)(m0 + tr*8)*HID + n0 + tc*8;
    #pragma unroll
    for (int i = 0; i < 8; i++){
        float o[8];
        #pragma unroll
        for (int j = 0; j < 4; j++) unpack2(acc2[i][j], o[2*j], o[2*j+1]);
        *(float4*)(Op + (size_t)i*HID)     = make_float4(o[0], o[1], o[2], o[3]);
        *(float4*)(Op + (size_t)i*HID + 4) = make_float4(o[4], o[5], o[6], o[7]);
    }
}

// ---------------- K6: s1 = Wh . a_out[:768], s2 = Wh . a_out[768:] -----------
__global__ void k_s12(const float* __restrict__ aout){
    int tid = threadIdx.x, lane = tid & 31, wi = tid >> 5;
    int row = blockIdx.x*8 + wi;
    const float* Whp = g_Wh + (size_t)row*HID;
    float s1 = 0.f, s2 = 0.f;
    for (int c = lane; c < HID; c += 32){
        float w = Whp[c];
        s1 += w * aout[c];
        s2 += w * aout[HID + c];
    }
    #pragma unroll
    for (int o = 16; o; o >>= 1){
        s1 += __shfl_xor_sync(0xffffffffu, s1, o);
        s2 += __shfl_xor_sync(0xffffffffu, s2, o);
    }
    if (lane == 0){ g_s1[row] = s1; g_s2[row] = s2; }
}

// ---------------- K7: fused masked-softmax attention GEMM + elu + mean pool --
__global__ void __launch_bounds__(256,2) k_attn(float* __restrict__ out){
    __shared__ float Whs[32][128];
    __shared__ float Aw [32][128];
    __shared__ float denS[256];
    __shared__ float colsum[128];
    int it = blockIdx.x, ct = blockIdx.y, b = blockIdx.z;
    int tid = threadIdx.x;
    int r = tid & 127, half = tid >> 7;
    int rowbase = b*NN + it*128;
    float s1r = g_s1[rowbase + r];
    const unsigned* abp = g_adjbits + (size_t)(rowbase + r)*64;
    const float* s2p = g_s2 + b*NN;
    int lkk = tid >> 3;              // 0..31 (Wh load row)
    int lc  = (tid & 7) * 16;        // Wh load col group
    const float* WhB = g_Wh + (size_t)b*NN*HID + ct*128;
    int tr = tid >> 4, tc = tid & 15;
    if (tid < 128) colsum[tid] = 0.f;
    u64 acc2[8][4];
    #pragma unroll
    for (int i = 0; i < 8; i++)
        #pragma unroll
        for (int j = 0; j < 4; j++) acc2[i][j] = 0ull;
    float dpart = 0.f;
    for (int kt = 0; kt < 64; kt++){
        const float* wp = WhB + (size_t)(kt*32 + lkk)*HID + lc;
        float4 w0 = *(const float4*)wp;
        float4 w1 = *(const float4*)(wp + 4);
        float4 w2 = *(const float4*)(wp + 8);
        float4 w3 = *(const float4*)(wp + 12);
        // generate attention weights while loads are in flight
        unsigned word = abp[kt];
        #pragma unroll
        for (int q = 0; q < 16; q++){
            int kk = half*16 + q;
            float w = 0.f;
            if ((word >> kk) & 1u){
                w = __expf(leakyf(s1r + s2p[kt*32 + kk]));
                dpart += w;
            }
            Aw[kk][r] = w;
        }
        *(float4*)&Whs[lkk][lc]      = w0;
        *(float4*)&Whs[lkk][lc + 4]  = w1;
        *(float4*)&Whs[lkk][lc + 8]  = w2;
        *(float4*)&Whs[lkk][lc + 12] = w3;
        __syncthreads();
        #pragma unroll
        for (int kk = 0; kk < 32; kk++){
            float av[8];
            *(float4*)av     = *(float4*)&Aw[kk][tr*8];
            *(float4*)(av+4) = *(float4*)&Aw[kk][tr*8+4];
            u64 b2[4];
            ulonglong2 t0 = *(const ulonglong2*)&Whs[kk][tc*8];
            ulonglong2 t1 = *(const ulonglong2*)&Whs[kk][tc*8+4];
            b2[0]=t0.x; b2[1]=t0.y; b2[2]=t1.x; b2[3]=t1.y;
            #pragma unroll
            for (int i = 0; i < 8; i++){
                u64 a2 = pack2(av[i], av[i]);
                #pragma unroll
                for (int j = 0; j < 4; j++) fma2(acc2[i][j], a2, b2[j]);
            }
        }
        __syncthreads();
    }
    denS[tid] = dpart;
    __syncthreads();
    float csum[8];
    #pragma unroll
    for (int j = 0; j < 8; j++) csum[j] = 0.f;
    #pragma unroll
    for (int i = 0; i < 8; i++){
        int lr = tr*8 + i;
        float den = denS[lr] + denS[128 + lr];
        float inv = (den > 0.f) ? 1.f/den : 0.f;
        float o[8];
        #pragma unroll
        for (int j = 0; j < 4; j++) unpack2(acc2[i][j], o[2*j], o[2*j+1]);
        #pragma unroll
        for (int j = 0; j < 8; j++) csum[j] += eluf(o[j] * inv);
    }
    #pragma unroll
    for (int j = 0; j < 8; j++) atomicAdd(&colsum[tc*8 + j], csum[j]);
    __syncthreads();
    if (tid < 128)
        atomicAdd(&out[b*HID + ct*128 + tid], colsum[tid] * (1.f/(float)NN));
}

// ---------------- launch ------------------------------------------------------
extern "C" void kernel_launch(void* const* d_in, const int* in_sizes, int n_in,
                              void* d_out, int out_size){
    const int*   nf     = (const int*)d_in[0];
    const int*   adj    = (const int*)d_in[1];
    const float* embed  = (const float*)d_in[2];
    const float* Wheads = (const float*)d_in[3];
    const float* aheads = (const float*)d_in[4];
    const float* Wout   = (const float*)d_in[5];
    const float* aout   = (const float*)d_in[6];
    float* out = (float*)d_out;

    k_zero<<<24, 256>>>(out);
    k_T  <<<dim3(6, 4), 128>>>(embed, Wheads);
    k_pre2<<<1, 64>>>(aheads);
    k_adj<<<2048, 256>>>(nf, adj);
    k_l1 <<<dim3(128, 24), 256>>>(nf);
    k_gemm<<<dim3(6, 128), 256>>>(Wout);
    k_s12<<<2048, 256>>>(aout);
    k_attn<<<dim3(16, 6, 8), 256>>>(out);
}